// round 1
// baseline (speedup 1.0000x reference)
#include <cuda_runtime.h>

#define NMAX 50000
#define EMAX 800000
#define E2MAX (EMAX + NMAX)
#define HC 160
#define NH 5
#define NC 32

// ---- scratch (static device globals; no allocation allowed) ----
__device__ __align__(16) float g_h1[NMAX * HC];    // layer1 node features [N,5,32]
__device__ __align__(16) float g_agg1[NMAX * HC];  // layer1 aggregation
__device__ float g_as1[NMAX * NH], g_ad1[NMAX * NH];
__device__ float g_ex[E2MAX * NH];                 // exp(logits), reused across layers
__device__ float g_den1[NMAX * NH], g_den2[NMAX * NH];
__device__ float g_h2[NMAX * NH], g_as2[NMAX * NH], g_ad2[NMAX * NH];
__device__ float g_agg2[NMAX * NH];
__device__ float g_ce1[NH], g_ce2[NH];
__device__ float g_easum;

// ---- zero accumulators ----
__global__ void k_zero(int N) {
    long stride = (long)gridDim.x * blockDim.x;
    long i0 = (long)blockIdx.x * blockDim.x + threadIdx.x;
    for (long i = i0; i < (long)N * HC; i += stride) g_agg1[i] = 0.f;
    for (long i = i0; i < (long)N * NH; i += stride) {
        g_den1[i] = 0.f; g_den2[i] = 0.f; g_agg2[i] = 0.f;
    }
    if (i0 == 0) g_easum = 0.f;
}

// ---- edge_attr sum (for self-loop fill value = mean) ----
__global__ void k_easum(const float* __restrict__ ea, int E) {
    float s = 0.f;
    for (int i = blockIdx.x * blockDim.x + threadIdx.x; i < E; i += gridDim.x * blockDim.x)
        s += ea[i];
    #pragma unroll
    for (int o = 16; o; o >>= 1) s += __shfl_xor_sync(~0u, s, o);
    __shared__ float ws[8];
    int w = threadIdx.x >> 5;
    if ((threadIdx.x & 31) == 0) ws[w] = s;
    __syncthreads();
    if (threadIdx.x == 0) {
        float t = 0.f;
        for (int i = 0; i < (int)(blockDim.x >> 5); i++) t += ws[i];
        atomicAdd(&g_easum, t);
    }
}

// ---- per-head edge-attention constants: ce[h] = sum_c We[h,c]*ae[h,c] ----
__global__ void k_ce(const float* __restrict__ We1, const float* __restrict__ ae1,
                     const float* __restrict__ We2, const float* __restrict__ ae2) {
    int h = threadIdx.x;
    if (h < NH) {
        float s = 0.f;
        for (int c = 0; c < NC; c++) s += We1[h * NC + c] * ae1[h * NC + c];
        g_ce1[h] = s;
        g_ce2[h] = We2[h] * ae2[h];
    }
}

// ---- layer1 node transform: h1 = x@W1, alpha_s/alpha_d dots. warp per node ----
__global__ void k_node1(const float* __restrict__ x, const float* __restrict__ W1,
                        const float* __restrict__ asrc, const float* __restrict__ adst, int N) {
    int warp = (blockIdx.x * blockDim.x + threadIdx.x) >> 5;
    int lane = threadIdx.x & 31;
    if (warp >= N) return;
    int n = warp;
    float xf[5];
    #pragma unroll
    for (int f = 0; f < 5; f++) xf[f] = __ldg(&x[n * 5 + f]);
    #pragma unroll
    for (int h = 0; h < NH; h++) {
        int col = h * NC + lane;
        float acc = 0.f;
        #pragma unroll
        for (int f = 0; f < 5; f++) acc = fmaf(xf[f], __ldg(&W1[f * HC + col]), acc);
        g_h1[(long)n * HC + col] = acc;
        float ps = acc * __ldg(&asrc[col]);
        float pd = acc * __ldg(&adst[col]);
        #pragma unroll
        for (int o = 16; o; o >>= 1) {
            ps += __shfl_xor_sync(~0u, ps, o);
            pd += __shfl_xor_sync(~0u, pd, o);
        }
        if (lane == 0) { g_as1[n * NH + h] = ps; g_ad1[n * NH + h] = pd; }
    }
}

// ---- edge logits + softmax denominators (no max-shift: shift-invariant) ----
template <int L>
__global__ void k_edge_logits(const int* __restrict__ src, const int* __restrict__ dst,
                              const float* __restrict__ ea, int E, int N, float invE) {
    int e = blockIdx.x * blockDim.x + threadIdx.x;
    int E2 = E + N;
    if (e >= E2) return;
    const float* asv = (L == 1) ? g_as1 : g_as2;
    const float* adv = (L == 1) ? g_ad1 : g_ad2;
    const float* ce  = (L == 1) ? g_ce1 : g_ce2;
    float* den       = (L == 1) ? g_den1 : g_den2;
    int s, d; float av;
    if (e < E) { s = __ldg(&src[e]); d = __ldg(&dst[e]); av = __ldg(&ea[e]); }
    else       { s = d = e - E; av = g_easum * invE; }
    #pragma unroll
    for (int h = 0; h < NH; h++) {
        float l = __ldg(&asv[s * NH + h]) + __ldg(&adv[d * NH + h]) + av * ce[h];
        l = l > 0.f ? l : 0.2f * l;           // leaky_relu(0.2)
        float ex = __expf(l);
        g_ex[(long)e * NH + h] = ex;
        atomicAdd(&den[d * NH + h], ex);
    }
}

// ---- layer1 aggregation: warp per edge, vector red.v4 into agg1 ----
__global__ void k_agg1(const int* __restrict__ src, const int* __restrict__ dst, int E, int N) {
    int gid = blockIdx.x * blockDim.x + threadIdx.x;
    int warp = gid >> 5, lane = gid & 31;
    int E2 = E + N;
    if (warp >= E2) return;
    int e = warp, s, d;
    if (e < E) { s = __ldg(&src[e]); d = __ldg(&dst[e]); }
    else       { s = d = e - E; }
    float aval = 0.f;
    if (lane < NH) aval = g_ex[(long)e * NH + lane] / (g_den1[d * NH + lane] + 1e-16f);
    const float4* hrow = (const float4*)(g_h1 + (long)s * HC);
    float* arow = g_agg1 + (long)d * HC;
    // first 32 of 40 float4 groups
    {
        int idx = lane;
        float a = __shfl_sync(~0u, aval, idx >> 3);
        float4 v = __ldg(hrow + idx);
        v.x *= a; v.y *= a; v.z *= a; v.w *= a;
        asm volatile("red.global.add.v4.f32 [%0], {%1,%2,%3,%4};"
                     :: "l"(arow + idx * 4), "f"(v.x), "f"(v.y), "f"(v.z), "f"(v.w) : "memory");
    }
    float a4 = __shfl_sync(~0u, aval, 4);
    if (lane < 8) {
        int idx = 32 + lane;
        float4 v = __ldg(hrow + idx);
        v.x *= a4; v.y *= a4; v.z *= a4; v.w *= a4;
        asm volatile("red.global.add.v4.f32 [%0], {%1,%2,%3,%4};"
                     :: "l"(arow + idx * 4), "f"(v.x), "f"(v.y), "f"(v.z), "f"(v.w) : "memory");
    }
}

// ---- layer2 node transform: x2=relu(agg1+b1); h2=x2@W2; attn dots. warp/node ----
__global__ void k_node2(const float* __restrict__ W2, const float* __restrict__ b1,
                        const float* __restrict__ as2w, const float* __restrict__ ad2w, int N) {
    int warp = (blockIdx.x * blockDim.x + threadIdx.x) >> 5;
    int lane = threadIdx.x & 31;
    if (warp >= N) return;
    int n = warp;
    float acc[NH] = {0.f, 0.f, 0.f, 0.f, 0.f};
    #pragma unroll
    for (int i = 0; i < 5; i++) {
        int k = i * 32 + lane;
        float v = g_agg1[(long)n * HC + k] + __ldg(&b1[k]);
        v = fmaxf(v, 0.f);
        #pragma unroll
        for (int h = 0; h < NH; h++) acc[h] = fmaf(v, __ldg(&W2[k * NH + h]), acc[h]);
    }
    #pragma unroll
    for (int h = 0; h < NH; h++)
        #pragma unroll
        for (int o = 16; o; o >>= 1) acc[h] += __shfl_xor_sync(~0u, acc[h], o);
    if (lane == 0) {
        #pragma unroll
        for (int h = 0; h < NH; h++) {
            g_h2[n * NH + h]  = acc[h];
            g_as2[n * NH + h] = acc[h] * __ldg(&as2w[h]);
            g_ad2[n * NH + h] = acc[h] * __ldg(&ad2w[h]);
        }
    }
}

// ---- layer2 aggregation: thread per edge, 5 scalar atomics ----
__global__ void k_agg2(const int* __restrict__ src, const int* __restrict__ dst, int E, int N) {
    int e = blockIdx.x * blockDim.x + threadIdx.x;
    int E2 = E + N;
    if (e >= E2) return;
    int s, d;
    if (e < E) { s = __ldg(&src[e]); d = __ldg(&dst[e]); }
    else       { s = d = e - E; }
    #pragma unroll
    for (int h = 0; h < NH; h++) {
        float a = g_ex[(long)e * NH + h] / (g_den2[d * NH + h] + 1e-16f);
        atomicAdd(&g_agg2[d * NH + h], a * __ldg(&g_h2[s * NH + h]));
    }
}

// ---- final: mean over heads + b2, Wlin, sigmoid ----
__global__ void k_final(const float* __restrict__ b2, const float* __restrict__ Wlin,
                        float* __restrict__ out, int N) {
    int n = blockIdx.x * blockDim.x + threadIdx.x;
    if (n >= N) return;
    float s = 0.f;
    #pragma unroll
    for (int h = 0; h < NH; h++) s += g_agg2[n * NH + h];
    float y = (s * (1.0f / NH) + __ldg(&b2[0])) * __ldg(&Wlin[0]);
    out[n] = 1.0f / (1.0f + expf(-y));
}

extern "C" void kernel_launch(void* const* d_in, const int* in_sizes, int n_in,
                              void* d_out, int out_size) {
    const float* x      = (const float*)d_in[0];
    const float* ea     = (const float*)d_in[1];
    const int*   src    = (const int*)d_in[2];
    const int*   dst    = (const int*)d_in[3];
    const float* W1     = (const float*)d_in[4];
    const float* a_src1 = (const float*)d_in[5];
    const float* a_dst1 = (const float*)d_in[6];
    const float* We1    = (const float*)d_in[7];
    const float* ae1    = (const float*)d_in[8];
    const float* b1     = (const float*)d_in[9];
    const float* W2     = (const float*)d_in[10];
    const float* a_src2 = (const float*)d_in[11];
    const float* a_dst2 = (const float*)d_in[12];
    const float* We2    = (const float*)d_in[13];
    const float* ae2    = (const float*)d_in[14];
    const float* b2     = (const float*)d_in[15];
    const float* Wlin   = (const float*)d_in[16];

    int N  = in_sizes[0] / 5;
    int E  = in_sizes[2];
    int E2 = E + N;
    float invE = 1.0f / (float)E;

    k_zero<<<2048, 256>>>(N);
    k_easum<<<512, 256>>>(ea, E);
    k_ce<<<1, 32>>>(We1, ae1, We2, ae2);
    k_node1<<<(N * 32 + 255) / 256, 256>>>(x, W1, a_src1, a_dst1, N);
    k_edge_logits<1><<<(E2 + 255) / 256, 256>>>(src, dst, ea, E, N, invE);
    k_agg1<<<(int)(((long)E2 * 32 + 255) / 256), 256>>>(src, dst, E, N);
    k_node2<<<(N * 32 + 255) / 256, 256>>>(W2, b1, a_src2, a_dst2, N);
    k_edge_logits<2><<<(E2 + 255) / 256, 256>>>(src, dst, ea, E, N, invE);
    k_agg2<<<(E2 + 255) / 256, 256>>>(src, dst, E, N);
    k_final<<<(N + 255) / 256, 256>>>(b2, Wlin, (float*)d_out, N);
}

// round 2
// speedup vs baseline: 1.2138x; 1.2138x over previous
#include <cuda_runtime.h>

#define NMAX 50000
#define EMAX 800000
#define E2MAX (EMAX + NMAX)
#define HC 160
#define NH 5
#define NC 32

// ---- scratch (static device globals) ----
__device__ __align__(16) float g_h1[NMAX * HC];
__device__ float g_as1[NMAX * NH], g_ad1[NMAX * NH];
__device__ float g_h2[NMAX * NH], g_as2[NMAX * NH], g_ad2[NMAX * NH];
__device__ float g_ce1[NH], g_ce2[NH];
__device__ float g_easum;
__device__ int   g_cnt[NMAX];
__device__ int   g_rowptr[NMAX + 1];
__device__ int   g_wp[NMAX];
__device__ int   g_csrc[E2MAX];
__device__ float g_cea[E2MAX];

// ---- init: zero counters ----
__global__ void k_init(int N) {
    int i = blockIdx.x * blockDim.x + threadIdx.x;
    if (i < N) g_cnt[i] = 0;
    if (i == 0) g_easum = 0.f;
}

// ---- count in-degree (incl self-loops) + edge_attr sum ----
__global__ void k_count(const int* __restrict__ dst, const float* __restrict__ ea,
                        int E, int N) {
    int e = blockIdx.x * blockDim.x + threadIdx.x;
    int E2 = E + N;
    float s = 0.f;
    if (e < E2) {
        int d = (e < E) ? __ldg(&dst[e]) : (e - E);
        atomicAdd(&g_cnt[d], 1);
        if (e < E) s = __ldg(&ea[e]);
    }
    #pragma unroll
    for (int o = 16; o; o >>= 1) s += __shfl_xor_sync(~0u, s, o);
    if ((threadIdx.x & 31) == 0 && s != 0.f) atomicAdd(&g_easum, s);
}

// ---- exclusive scan over g_cnt (single block) + per-head attn constants ----
__global__ void k_scan(const float* __restrict__ We1, const float* __restrict__ ae1,
                       const float* __restrict__ We2, const float* __restrict__ ae2,
                       int N, int E2) {
    __shared__ int sm[1024];
    int t = threadIdx.x;
    if (t < NH) {
        float s = 0.f;
        for (int c = 0; c < NC; c++) s += We1[t * NC + c] * ae1[t * NC + c];
        g_ce1[t] = s;
        g_ce2[t] = We2[t] * ae2[t];
    }
    int chunk = (N + 1023) / 1024;
    int b = t * chunk, e = min(b + chunk, N);
    int s = 0;
    for (int i = b; i < e; i++) s += g_cnt[i];
    sm[t] = s;
    __syncthreads();
    for (int off = 1; off < 1024; off <<= 1) {
        int v = (t >= off) ? sm[t - off] : 0;
        __syncthreads();
        sm[t] += v;
        __syncthreads();
    }
    int run = t ? sm[t - 1] : 0;
    for (int i = b; i < e; i++) {
        g_rowptr[i] = run; g_wp[i] = run;
        run += g_cnt[i];
    }
    if (t == 0) g_rowptr[N] = E2;
}

// ---- scatter edges into CSR (by dst) ----
__global__ void k_scatter(const int* __restrict__ src, const int* __restrict__ dst,
                          const float* __restrict__ ea, int E, int N, float invE) {
    int e = blockIdx.x * blockDim.x + threadIdx.x;
    int E2 = E + N;
    if (e >= E2) return;
    int s, d; float av;
    if (e < E) { s = __ldg(&src[e]); d = __ldg(&dst[e]); av = __ldg(&ea[e]); }
    else       { s = d = e - E; av = g_easum * invE; }
    int pos = atomicAdd(&g_wp[d], 1);
    g_csrc[pos] = s;
    g_cea[pos] = av;
}

// ---- layer1 node transform: h1 = x@W1 + attn dots. warp per node ----
__global__ void k_node1(const float* __restrict__ x, const float* __restrict__ W1,
                        const float* __restrict__ asrc, const float* __restrict__ adst, int N) {
    int warp = (blockIdx.x * blockDim.x + threadIdx.x) >> 5;
    int lane = threadIdx.x & 31;
    if (warp >= N) return;
    int n = warp;
    float xf[5];
    #pragma unroll
    for (int f = 0; f < 5; f++) xf[f] = __ldg(&x[n * 5 + f]);
    #pragma unroll
    for (int h = 0; h < NH; h++) {
        int col = h * NC + lane;
        float acc = 0.f;
        #pragma unroll
        for (int f = 0; f < 5; f++) acc = fmaf(xf[f], __ldg(&W1[f * HC + col]), acc);
        g_h1[(long)n * HC + col] = acc;
        float ps = acc * __ldg(&asrc[col]);
        float pd = acc * __ldg(&adst[col]);
        #pragma unroll
        for (int o = 16; o; o >>= 1) {
            ps += __shfl_xor_sync(~0u, ps, o);
            pd += __shfl_xor_sync(~0u, pd, o);
        }
        if (lane == 0) { g_as1[n * NH + h] = ps; g_ad1[n * NH + h] = pd; }
    }
}

// ---- FUSED: layer1 softmax+agg (gather) + relu + layer2 node transform ----
// warp per destination node; lanes cooperate across the 160 channels.
__global__ void k_fused1(const float* __restrict__ b1, const float* __restrict__ W2,
                         const float* __restrict__ as2w, const float* __restrict__ ad2w,
                         int N) {
    int warp = (blockIdx.x * blockDim.x + threadIdx.x) >> 5;
    int lane = threadIdx.x & 31;
    if (warp >= N) return;
    int n = warp;
    int row = g_rowptr[n], end = g_rowptr[n + 1];

    float adl = 0.f, cel = 0.f;
    if (lane < NH) {
        adl = g_ad1[n * NH + lane];
        cel = g_ce1[lane];
    }
    float acc[5] = {0.f, 0.f, 0.f, 0.f, 0.f};
    float den = 0.f;

    int e = row;
    int s = 0; float av = 0.f;
    if (e < end) { s = g_csrc[e]; av = g_cea[e]; }
    while (e < end) {
        int e1 = e + 1;
        int s_n = 0; float av_n = 0.f;
        if (e1 < end) { s_n = g_csrc[e1]; av_n = g_cea[e1]; }
        float exl = 0.f;
        if (lane < NH) {
            float l = g_as1[s * NH + lane] + adl + av * cel;
            l = l > 0.f ? l : 0.2f * l;
            exl = __expf(l);
            den += exl;
        }
        const float* hrow = g_h1 + (long)s * HC;
        #pragma unroll
        for (int i = 0; i < 5; i++) {
            float ex_i = __shfl_sync(~0u, exl, i);
            float v = __ldg(&hrow[lane + 32 * i]);
            acc[i] = fmaf(ex_i, v, acc[i]);
        }
        s = s_n; av = av_n; e = e1;
    }

    // finalize softmax + relu(+b1) -> x2 (in registers), then x2 @ W2
    float a2[NH] = {0.f, 0.f, 0.f, 0.f, 0.f};
    #pragma unroll
    for (int i = 0; i < 5; i++) {
        float d_i = __shfl_sync(~0u, den, i);
        int k = lane + 32 * i;
        float v = acc[i] / (d_i + 1e-16f) + __ldg(&b1[k]);
        v = fmaxf(v, 0.f);
        #pragma unroll
        for (int h = 0; h < NH; h++)
            a2[h] = fmaf(v, __ldg(&W2[k * NH + h]), a2[h]);
    }
    #pragma unroll
    for (int h = 0; h < NH; h++)
        #pragma unroll
        for (int o = 16; o; o >>= 1) a2[h] += __shfl_xor_sync(~0u, a2[h], o);
    if (lane == 0) {
        #pragma unroll
        for (int h = 0; h < NH; h++) {
            g_h2[n * NH + h]  = a2[h];
            g_as2[n * NH + h] = a2[h] * __ldg(&as2w[h]);
            g_ad2[n * NH + h] = a2[h] * __ldg(&ad2w[h]);
        }
    }
}

// ---- FUSED: layer2 softmax+agg + head-mean + Wlin + sigmoid ----
// warp per destination node; lane per edge.
__global__ void k_fused2(const float* __restrict__ b2, const float* __restrict__ Wlin,
                         float* __restrict__ out, int N) {
    int warp = (blockIdx.x * blockDim.x + threadIdx.x) >> 5;
    int lane = threadIdx.x & 31;
    if (warp >= N) return;
    int n = warp;
    int row = g_rowptr[n], end = g_rowptr[n + 1];

    float adh[NH], ceh[NH];
    #pragma unroll
    for (int h = 0; h < NH; h++) {
        adh[h] = g_ad2[n * NH + h];
        ceh[h] = g_ce2[h];
    }
    float acch[NH] = {0.f, 0.f, 0.f, 0.f, 0.f};
    float denh[NH] = {0.f, 0.f, 0.f, 0.f, 0.f};

    for (int base = row; base < end; base += 32) {
        int e = base + lane;
        if (e < end) {
            int s = g_csrc[e];
            float av = g_cea[e];
            #pragma unroll
            for (int h = 0; h < NH; h++) {
                float l = g_as2[s * NH + h] + adh[h] + av * ceh[h];
                l = l > 0.f ? l : 0.2f * l;
                float ex = __expf(l);
                denh[h] += ex;
                acch[h] = fmaf(ex, g_h2[s * NH + h], acch[h]);
            }
        }
    }
    #pragma unroll
    for (int h = 0; h < NH; h++)
        #pragma unroll
        for (int o = 16; o; o >>= 1) {
            acch[h] += __shfl_xor_sync(~0u, acch[h], o);
            denh[h] += __shfl_xor_sync(~0u, denh[h], o);
        }
    if (lane == 0) {
        float ssum = 0.f;
        #pragma unroll
        for (int h = 0; h < NH; h++) ssum += acch[h] / (denh[h] + 1e-16f);
        float y = (ssum * (1.0f / NH) + __ldg(&b2[0])) * __ldg(&Wlin[0]);
        out[n] = 1.0f / (1.0f + expf(-y));
    }
}

extern "C" void kernel_launch(void* const* d_in, const int* in_sizes, int n_in,
                              void* d_out, int out_size) {
    const float* x      = (const float*)d_in[0];
    const float* ea     = (const float*)d_in[1];
    const int*   src    = (const int*)d_in[2];
    const int*   dst    = (const int*)d_in[3];
    const float* W1     = (const float*)d_in[4];
    const float* a_src1 = (const float*)d_in[5];
    const float* a_dst1 = (const float*)d_in[6];
    const float* We1    = (const float*)d_in[7];
    const float* ae1    = (const float*)d_in[8];
    const float* b1     = (const float*)d_in[9];
    const float* W2     = (const float*)d_in[10];
    const float* a_src2 = (const float*)d_in[11];
    const float* a_dst2 = (const float*)d_in[12];
    const float* We2    = (const float*)d_in[13];
    const float* ae2    = (const float*)d_in[14];
    const float* b2     = (const float*)d_in[15];
    const float* Wlin   = (const float*)d_in[16];

    int N  = in_sizes[0] / 5;
    int E  = in_sizes[2];
    int E2 = E + N;
    float invE = 1.0f / (float)E;

    k_init<<<(N + 255) / 256, 256>>>(N);
    k_count<<<(E2 + 255) / 256, 256>>>(dst, ea, E, N);
    k_scan<<<1, 1024>>>(We1, ae1, We2, ae2, N, E2);
    k_scatter<<<(E2 + 255) / 256, 256>>>(src, dst, ea, E, N, invE);
    k_node1<<<(N * 32 + 255) / 256, 256>>>(x, W1, a_src1, a_dst1, N);
    k_fused1<<<(N * 32 + 255) / 256, 256>>>(b1, W2, a_src2, a_dst2, N);
    k_fused2<<<(N * 32 + 255) / 256, 256>>>(b2, Wlin, (float*)d_out, N);
}

// round 3
// speedup vs baseline: 1.2812x; 1.0555x over previous
#include <cuda_runtime.h>
#include <cuda_fp16.h>

#define NMAX 50000
#define EMAX 800000
#define E2MAX (EMAX + NMAX)
#define HC 160
#define NH 5
#define NC 32

// ---- scratch (static device globals) ----
__device__ __align__(16) __half g_h1h[NMAX * HC];     // layer1 features, fp16
__device__ float g_as1[NMAX * NH], g_ad1[NMAX * NH];
__device__ __align__(8) float2 g_h2as2[NMAX * NH];    // {h2, as2} interleaved
__device__ float g_ad2[NMAX * NH];
__device__ float g_ce1[NH], g_ce2[NH];
__device__ float g_easum;
__device__ int   g_cnt[NMAX];
__device__ int   g_rowptr[NMAX + 1];
__device__ int   g_wp[NMAX];
__device__ __align__(8) int2 g_edge[E2MAX];           // {src, ea-bits}

// ---- combo: [count in-degree + easum]  ||  [node1 transform] ----
__global__ void k_combo(const int* __restrict__ dst, const float* __restrict__ ea,
                        const float* __restrict__ x, const float* __restrict__ W1,
                        const float* __restrict__ asrc, const float* __restrict__ adst,
                        int E, int N, int countBlocks) {
    if ((int)blockIdx.x < countBlocks) {
        // ---- counting part ----
        int e = blockIdx.x * blockDim.x + threadIdx.x;
        int E2 = E + N;
        float s = 0.f;
        if (e < E2) {
            int d = (e < E) ? __ldg(&dst[e]) : (e - E);
            atomicAdd(&g_cnt[d], 1);
            if (e < E) s = __ldg(&ea[e]);
        }
        #pragma unroll
        for (int o = 16; o; o >>= 1) s += __shfl_xor_sync(~0u, s, o);
        if ((threadIdx.x & 31) == 0 && s != 0.f) atomicAdd(&g_easum, s);
    } else {
        // ---- node1: h1 = x@W1 (fp16 out) + attention dots ----
        int warp = (((int)blockIdx.x - countBlocks) * blockDim.x + threadIdx.x) >> 5;
        int lane = threadIdx.x & 31;
        if (warp >= N) return;
        int n = warp;
        float xf[5];
        #pragma unroll
        for (int f = 0; f < 5; f++) xf[f] = __ldg(&x[n * 5 + f]);
        #pragma unroll
        for (int h = 0; h < NH; h++) {
            int col = h * NC + lane;
            float acc = 0.f;
            #pragma unroll
            for (int f = 0; f < 5; f++) acc = fmaf(xf[f], __ldg(&W1[f * HC + col]), acc);
            g_h1h[(size_t)n * HC + col] = __float2half(acc);
            float ps = acc * __ldg(&asrc[col]);
            float pd = acc * __ldg(&adst[col]);
            #pragma unroll
            for (int o = 16; o; o >>= 1) {
                ps += __shfl_xor_sync(~0u, ps, o);
                pd += __shfl_xor_sync(~0u, pd, o);
            }
            if (lane == 0) { g_as1[n * NH + h] = ps; g_ad1[n * NH + h] = pd; }
        }
    }
}

// ---- exclusive scan over g_cnt (single block) + per-head attn constants ----
__global__ void k_scan(const float* __restrict__ We1, const float* __restrict__ ae1,
                       const float* __restrict__ We2, const float* __restrict__ ae2,
                       int N, int E2) {
    __shared__ int sm[1024];
    int t = threadIdx.x;
    if (t < NH) {
        float s = 0.f;
        for (int c = 0; c < NC; c++) s += We1[t * NC + c] * ae1[t * NC + c];
        g_ce1[t] = s;
        g_ce2[t] = We2[t] * ae2[t];
    }
    int chunk = (N + 1023) / 1024;
    int b = t * chunk, e = min(b + chunk, N);
    int s = 0;
    for (int i = b; i < e; i++) s += g_cnt[i];
    sm[t] = s;
    __syncthreads();
    for (int off = 1; off < 1024; off <<= 1) {
        int v = (t >= off) ? sm[t - off] : 0;
        __syncthreads();
        sm[t] += v;
        __syncthreads();
    }
    int run = t ? sm[t - 1] : 0;
    for (int i = b; i < e; i++) {
        g_rowptr[i] = run; g_wp[i] = run;
        run += g_cnt[i];
    }
    if (t == 0) g_rowptr[N] = E2;
}

// ---- scatter edges into CSR (by dst), packed 8B records ----
__global__ void k_scatter(const int* __restrict__ src, const int* __restrict__ dst,
                          const float* __restrict__ ea, int E, int N, float invE) {
    int e = blockIdx.x * blockDim.x + threadIdx.x;
    int E2 = E + N;
    if (e >= E2) return;
    int s, d; float av;
    if (e < E) { s = __ldg(&src[e]); d = __ldg(&dst[e]); av = __ldg(&ea[e]); }
    else       { s = d = e - E; av = g_easum * invE; }
    int pos = atomicAdd(&g_wp[d], 1);
    int2 rec; rec.x = s; rec.y = __float_as_int(av);
    g_edge[pos] = rec;
}

// ---- FUSED: layer1 softmax+agg (fp16 gather) + relu + layer2 transform ----
// warp per destination node. Channel map per lane l:
//   g0: c=2l,2l+1        head = l>>4
//   g1: c=64+2l,65+2l    head = 2+(l>>4)
//   g2 (l<16): c=128+2l,129+2l  head = 4
__global__ void k_fused1(const float* __restrict__ b1, const float* __restrict__ W2,
                         const float* __restrict__ as2w, const float* __restrict__ ad2w,
                         int N) {
    int warp = (blockIdx.x * blockDim.x + threadIdx.x) >> 5;
    int lane = threadIdx.x & 31;
    if (warp >= N) return;
    int n = warp;
    int row = g_rowptr[n], end = g_rowptr[n + 1];

    float adl = 0.f, cel = 0.f;
    if (lane < NH) {
        adl = g_ad1[n * NH + lane];
        cel = g_ce1[lane];
    }
    int hA = lane >> 4;        // head of g0
    int hB = 2 + hA;           // head of g1

    float ax0 = 0.f, ay0 = 0.f, ax1 = 0.f, ay1 = 0.f, ax2 = 0.f, ay2 = 0.f;
    float den = 0.f;

    int e = row;
    int2 r0, r1;
    if (e < end) r0 = g_edge[e];
    if (e + 1 < end) r1 = g_edge[e + 1];
    while (e < end) {
        int2 r2;
        if (e + 2 < end) r2 = g_edge[e + 2];
        int s = r0.x; float av = __int_as_float(r0.y);
        float exl = 0.f;
        if (lane < NH) {
            float l = __ldg(&g_as1[s * NH + lane]) + adl + av * cel;
            l = l > 0.f ? l : 0.2f * l;
            exl = __expf(l);
            den += exl;
        }
        float a0 = __shfl_sync(~0u, exl, hA);
        float a1 = __shfl_sync(~0u, exl, hB);
        float a2 = __shfl_sync(~0u, exl, 4);
        const __half2* hb = (const __half2*)(g_h1h + (size_t)s * HC);
        __half2 v0 = __ldg(&hb[lane]);
        __half2 v1 = __ldg(&hb[32 + lane]);
        float2 f0 = __half22float2(v0), f1 = __half22float2(v1);
        ax0 = fmaf(a0, f0.x, ax0); ay0 = fmaf(a0, f0.y, ay0);
        ax1 = fmaf(a1, f1.x, ax1); ay1 = fmaf(a1, f1.y, ay1);
        if (lane < 16) {
            __half2 v2 = __ldg(&hb[64 + lane]);
            float2 f2 = __half22float2(v2);
            ax2 = fmaf(a2, f2.x, ax2); ay2 = fmaf(a2, f2.y, ay2);
        }
        r0 = r1; r1 = r2; e++;
    }

    // softmax denominators per head
    float dA = __shfl_sync(~0u, den, hA);
    float dB = __shfl_sync(~0u, den, hB);
    float dC = __shfl_sync(~0u, den, 4);
    dA += 1e-16f; dB += 1e-16f; dC += 1e-16f;

    // x2 channels of this lane -> layer2 GEMV
    float a2h[NH] = {0.f, 0.f, 0.f, 0.f, 0.f};
    int k;
    float v;
    #define DO_CH(val, dd, kk) \
        k = (kk); v = (val) / (dd) + __ldg(&b1[k]); v = fmaxf(v, 0.f); \
        _Pragma("unroll") \
        for (int h = 0; h < NH; h++) a2h[h] = fmaf(v, __ldg(&W2[k * NH + h]), a2h[h]);
    DO_CH(ax0, dA, 2 * lane)
    DO_CH(ay0, dA, 2 * lane + 1)
    DO_CH(ax1, dB, 64 + 2 * lane)
    DO_CH(ay1, dB, 65 + 2 * lane)
    if (lane < 16) {
        DO_CH(ax2, dC, 128 + 2 * lane)
        DO_CH(ay2, dC, 129 + 2 * lane)
    }
    #undef DO_CH
    #pragma unroll
    for (int h = 0; h < NH; h++)
        #pragma unroll
        for (int o = 16; o; o >>= 1) a2h[h] += __shfl_xor_sync(~0u, a2h[h], o);
    if (lane == 0) {
        #pragma unroll
        for (int h = 0; h < NH; h++) {
            float2 p; p.x = a2h[h]; p.y = a2h[h] * __ldg(&as2w[h]);
            g_h2as2[n * NH + h] = p;
            g_ad2[n * NH + h] = a2h[h] * __ldg(&ad2w[h]);
        }
    }
}

// ---- FUSED: layer2 softmax+agg + head-mean + Wlin + sigmoid ----
__global__ void k_fused2(const float* __restrict__ b2, const float* __restrict__ Wlin,
                         float* __restrict__ out, int N) {
    int warp = (blockIdx.x * blockDim.x + threadIdx.x) >> 5;
    int lane = threadIdx.x & 31;
    if (warp >= N) return;
    int n = warp;
    int row = g_rowptr[n], end = g_rowptr[n + 1];

    float adh[NH], ceh[NH];
    #pragma unroll
    for (int h = 0; h < NH; h++) {
        adh[h] = g_ad2[n * NH + h];
        ceh[h] = g_ce2[h];
    }
    float acch[NH] = {0.f, 0.f, 0.f, 0.f, 0.f};
    float denh[NH] = {0.f, 0.f, 0.f, 0.f, 0.f};

    for (int base = row; base < end; base += 32) {
        int e = base + lane;
        if (e < end) {
            int2 r = g_edge[e];
            int s = r.x;
            float av = __int_as_float(r.y);
            #pragma unroll
            for (int h = 0; h < NH; h++) {
                float2 hs = g_h2as2[s * NH + h];   // {h2, as2}
                float l = hs.y + adh[h] + av * ceh[h];
                l = l > 0.f ? l : 0.2f * l;
                float ex = __expf(l);
                denh[h] += ex;
                acch[h] = fmaf(ex, hs.x, acch[h]);
            }
        }
    }
    #pragma unroll
    for (int h = 0; h < NH; h++)
        #pragma unroll
        for (int o = 16; o; o >>= 1) {
            acch[h] += __shfl_xor_sync(~0u, acch[h], o);
            denh[h] += __shfl_xor_sync(~0u, denh[h], o);
        }
    if (lane == 0) {
        float ssum = 0.f;
        #pragma unroll
        for (int h = 0; h < NH; h++) ssum += acch[h] / (denh[h] + 1e-16f);
        float y = (ssum * (1.0f / NH) + __ldg(&b2[0])) * __ldg(&Wlin[0]);
        out[n] = 1.0f / (1.0f + expf(-y));
    }
}

extern "C" void kernel_launch(void* const* d_in, const int* in_sizes, int n_in,
                              void* d_out, int out_size) {
    const float* x      = (const float*)d_in[0];
    const float* ea     = (const float*)d_in[1];
    const int*   src    = (const int*)d_in[2];
    const int*   dst    = (const int*)d_in[3];
    const float* W1     = (const float*)d_in[4];
    const float* a_src1 = (const float*)d_in[5];
    const float* a_dst1 = (const float*)d_in[6];
    const float* We1    = (const float*)d_in[7];
    const float* ae1    = (const float*)d_in[8];
    const float* b1     = (const float*)d_in[9];
    const float* W2     = (const float*)d_in[10];
    const float* a_src2 = (const float*)d_in[11];
    const float* a_dst2 = (const float*)d_in[12];
    const float* We2    = (const float*)d_in[13];
    const float* ae2    = (const float*)d_in[14];
    const float* b2     = (const float*)d_in[15];
    const float* Wlin   = (const float*)d_in[16];

    int N  = in_sizes[0] / 5;
    int E  = in_sizes[2];
    int E2 = E + N;
    float invE = 1.0f / (float)E;

    void* cntp = nullptr; void* easp = nullptr;
    cudaGetSymbolAddress(&cntp, g_cnt);
    cudaGetSymbolAddress(&easp, g_easum);
    cudaMemsetAsync(cntp, 0, N * sizeof(int));
    cudaMemsetAsync(easp, 0, sizeof(float));

    int countBlocks = (E2 + 255) / 256;
    int nodeBlocks  = (N * 32 + 255) / 256;
    k_combo<<<countBlocks + nodeBlocks, 256>>>(dst, ea, x, W1, a_src1, a_dst1, E, N, countBlocks);
    k_scan<<<1, 1024>>>(We1, ae1, We2, ae2, N, E2);
    k_scatter<<<(E2 + 255) / 256, 256>>>(src, dst, ea, E, N, invE);
    k_fused1<<<(N * 32 + 255) / 256, 256>>>(b1, W2, a_src2, a_dst2, N);
    k_fused2<<<(N * 32 + 255) / 256, 256>>>(b2, Wlin, (float*)d_out, N);
}

// round 4
// speedup vs baseline: 1.5671x; 1.2232x over previous
#include <cuda_runtime.h>
#include <cuda_fp16.h>

#define NMAX 50000
#define EMAX 800000
#define E2MAX (EMAX + NMAX)
#define HC 160
#define NH 5
#define NC 32
#define WPB 8   // warps per block in fused kernels

// ---- scratch (static device globals) ----
__device__ __align__(16) __half g_h1h[NMAX * HC];     // layer1 features, fp16
__device__ __align__(16) float g_as1[NMAX * 8];       // padded to 8 floats/node
__device__ float g_ad1[NMAX * NH];
__device__ __align__(16) float4 g_h2f4[NMAX * 3];     // {h2,as2}x5 padded to 48B
__device__ float g_ad2[NMAX * NH];
__device__ float g_ce1[NH], g_ce2[NH];
__device__ float g_easum;
__device__ int   g_cnt[NMAX];
__device__ int   g_rowptr[NMAX + 1];
__device__ int   g_pos[E2MAX];
__device__ __align__(8) int2 g_edge[E2MAX];           // {src, ea-bits}

// ---- combo: [count in-degree (save pos) + easum] || [node1 transform] ----
__global__ void k_combo(const int* __restrict__ dst, const float* __restrict__ ea,
                        const float* __restrict__ x, const float* __restrict__ W1,
                        const float* __restrict__ asrc, const float* __restrict__ adst,
                        int E, int N, int countBlocks) {
    if ((int)blockIdx.x < countBlocks) {
        int e = blockIdx.x * blockDim.x + threadIdx.x;
        int E2 = E + N;
        float s = 0.f;
        if (e < E2) {
            int d = (e < E) ? __ldg(&dst[e]) : (e - E);
            g_pos[e] = atomicAdd(&g_cnt[d], 1);
            if (e < E) s = __ldg(&ea[e]);
        }
        #pragma unroll
        for (int o = 16; o; o >>= 1) s += __shfl_xor_sync(~0u, s, o);
        if ((threadIdx.x & 31) == 0 && s != 0.f) atomicAdd(&g_easum, s);
    } else {
        int warp = (((int)blockIdx.x - countBlocks) * blockDim.x + threadIdx.x) >> 5;
        int lane = threadIdx.x & 31;
        if (warp >= N) return;
        int n = warp;
        float xf[5];
        #pragma unroll
        for (int f = 0; f < 5; f++) xf[f] = __ldg(&x[n * 5 + f]);
        #pragma unroll
        for (int h = 0; h < NH; h++) {
            int col = h * NC + lane;
            float acc = 0.f;
            #pragma unroll
            for (int f = 0; f < 5; f++) acc = fmaf(xf[f], __ldg(&W1[f * HC + col]), acc);
            g_h1h[(size_t)n * HC + col] = __float2half(acc);
            float ps = acc * __ldg(&asrc[col]);
            float pd = acc * __ldg(&adst[col]);
            #pragma unroll
            for (int o = 16; o; o >>= 1) {
                ps += __shfl_xor_sync(~0u, ps, o);
                pd += __shfl_xor_sync(~0u, pd, o);
            }
            if (lane == 0) { g_as1[n * 8 + h] = ps; g_ad1[n * NH + h] = pd; }
        }
    }
}

// ---- single-block exclusive scan (warp-shuffle hierarchy) + attn constants ----
__global__ void k_scan(const float* __restrict__ We1, const float* __restrict__ ae1,
                       const float* __restrict__ We2, const float* __restrict__ ae2,
                       int N, int E2) {
    __shared__ int wsum[32];
    int t = threadIdx.x;
    int lane = t & 31, w = t >> 5;
    if (t < NH) {
        float s = 0.f;
        for (int c = 0; c < NC; c++) s += We1[t * NC + c] * ae1[t * NC + c];
        g_ce1[t] = s;
        g_ce2[t] = We2[t] * ae2[t];
    }
    int chunk = (N + 1023) / 1024;
    int b = t * chunk, e = min(b + chunk, N);
    int s = 0;
    for (int i = b; i < e; i++) s += g_cnt[i];
    // inclusive warp scan
    int inc = s;
    #pragma unroll
    for (int o = 1; o < 32; o <<= 1) {
        int v = __shfl_up_sync(~0u, inc, o);
        if (lane >= o) inc += v;
    }
    if (lane == 31) wsum[w] = inc;
    __syncthreads();
    if (w == 0) {
        int v = wsum[lane];
        int iv = v;
        #pragma unroll
        for (int o = 1; o < 32; o <<= 1) {
            int u = __shfl_up_sync(~0u, iv, o);
            if (lane >= o) iv += u;
        }
        wsum[lane] = iv - v;   // exclusive warp offsets
    }
    __syncthreads();
    int run = wsum[w] + inc - s;   // exclusive prefix for this thread's chunk
    for (int i = b; i < e; i++) {
        g_rowptr[i] = run;
        run += g_cnt[i];
    }
    if (t == 0) g_rowptr[N] = E2;
}

// ---- scatter edges into CSR: atomic-free (pos precomputed) ----
__global__ void k_scatter(const int* __restrict__ src, const int* __restrict__ dst,
                          const float* __restrict__ ea, int E, int N, float invE) {
    int e = blockIdx.x * blockDim.x + threadIdx.x;
    int E2 = E + N;
    if (e >= E2) return;
    int s, d; float av;
    if (e < E) { s = __ldg(&src[e]); d = __ldg(&dst[e]); av = __ldg(&ea[e]); }
    else       { s = d = e - E; av = g_easum * invE; }
    int2 rec; rec.x = s; rec.y = __float_as_int(av);
    g_edge[g_rowptr[d] + g_pos[e]] = rec;
}

// ---- FUSED1: layer1 softmax+agg + relu + layer2 transform ----
// warp per dst node; two-phase per 32-edge chunk:
//   A: lane-per-edge logits/exp (staged in smem), B: channel-parallel agg.
__global__ void k_fused1(const float* __restrict__ b1, const float* __restrict__ W2,
                         const float* __restrict__ as2w, const float* __restrict__ ad2w,
                         int N) {
    __shared__ float s_ex[WPB][32][NH];
    __shared__ int   s_src[WPB][32];
    int warp = (blockIdx.x * blockDim.x + threadIdx.x) >> 5;
    int lane = threadIdx.x & 31;
    int w = (threadIdx.x >> 5);
    if (warp >= N) return;
    int n = warp;
    int row = g_rowptr[n], end = g_rowptr[n + 1];

    float adh[NH], ceh[NH];
    #pragma unroll
    for (int h = 0; h < NH; h++) {
        adh[h] = __ldg(&g_ad1[n * NH + h]);
        ceh[h] = g_ce1[h];
    }
    int hA = lane >> 4;       // head for channel group 0
    int hB = 2 + hA;          // group 1

    float ax0 = 0.f, ay0 = 0.f, ax1 = 0.f, ay1 = 0.f, ax2 = 0.f, ay2 = 0.f;
    float denh[NH] = {0.f, 0.f, 0.f, 0.f, 0.f};

    for (int base = row; base < end; base += 32) {
        int cnt = min(32, end - base);
        // --- phase A: lane-parallel logits ---
        if (lane < cnt) {
            int2 r = g_edge[base + lane];
            int sA = r.x;
            float av = __int_as_float(r.y);
            float4 a4 = __ldg((const float4*)(g_as1 + sA * 8));
            float a5 = __ldg(&g_as1[sA * 8 + 4]);
            float lv[NH] = {a4.x, a4.y, a4.z, a4.w, a5};
            #pragma unroll
            for (int h = 0; h < NH; h++) {
                float l = lv[h] + adh[h] + av * ceh[h];
                l = l > 0.f ? l : 0.2f * l;
                float ex = __expf(l);
                denh[h] += ex;
                s_ex[w][lane][h] = ex;
            }
            s_src[w][lane] = sA;
        }
        __syncwarp();
        // --- phase B: channel-parallel aggregation ---
        for (int j = 0; j < cnt; j++) {
            int s = s_src[w][j];
            float a0 = s_ex[w][j][hA];
            float a1 = s_ex[w][j][hB];
            float a2 = s_ex[w][j][4];
            const __half2* hb = (const __half2*)(g_h1h + (size_t)s * HC);
            __half2 v0 = __ldg(&hb[lane]);
            __half2 v1 = __ldg(&hb[32 + lane]);
            float2 f0 = __half22float2(v0), f1 = __half22float2(v1);
            ax0 = fmaf(a0, f0.x, ax0); ay0 = fmaf(a0, f0.y, ay0);
            ax1 = fmaf(a1, f1.x, ax1); ay1 = fmaf(a1, f1.y, ay1);
            if (lane < 16) {
                __half2 v2 = __ldg(&hb[64 + lane]);
                float2 f2 = __half22float2(v2);
                ax2 = fmaf(a2, f2.x, ax2); ay2 = fmaf(a2, f2.y, ay2);
            }
        }
        __syncwarp();
    }

    // reduce denominators across lanes
    #pragma unroll
    for (int h = 0; h < NH; h++) {
        #pragma unroll
        for (int o = 16; o; o >>= 1) denh[h] += __shfl_xor_sync(~0u, denh[h], o);
        denh[h] += 1e-16f;
    }
    float dA = denh[hA], dB = denh[hB], dC = denh[4];

    // x2 channels -> layer2 GEMV
    float a2h[NH] = {0.f, 0.f, 0.f, 0.f, 0.f};
    int k; float v;
    #define DO_CH(val, dd, kk) \
        k = (kk); v = (val) / (dd) + __ldg(&b1[k]); v = fmaxf(v, 0.f); \
        _Pragma("unroll") \
        for (int h = 0; h < NH; h++) a2h[h] = fmaf(v, __ldg(&W2[k * NH + h]), a2h[h]);
    DO_CH(ax0, dA, 2 * lane)
    DO_CH(ay0, dA, 2 * lane + 1)
    DO_CH(ax1, dB, 64 + 2 * lane)
    DO_CH(ay1, dB, 65 + 2 * lane)
    if (lane < 16) {
        DO_CH(ax2, dC, 128 + 2 * lane)
        DO_CH(ay2, dC, 129 + 2 * lane)
    }
    #undef DO_CH
    #pragma unroll
    for (int h = 0; h < NH; h++)
        #pragma unroll
        for (int o = 16; o; o >>= 1) a2h[h] += __shfl_xor_sync(~0u, a2h[h], o);
    if (lane == 0) {
        float4 p0, p1, p2;
        p0.x = a2h[0]; p0.y = a2h[0] * __ldg(&as2w[0]);
        p0.z = a2h[1]; p0.w = a2h[1] * __ldg(&as2w[1]);
        p1.x = a2h[2]; p1.y = a2h[2] * __ldg(&as2w[2]);
        p1.z = a2h[3]; p1.w = a2h[3] * __ldg(&as2w[3]);
        p2.x = a2h[4]; p2.y = a2h[4] * __ldg(&as2w[4]);
        p2.z = 0.f; p2.w = 0.f;
        g_h2f4[n * 3 + 0] = p0;
        g_h2f4[n * 3 + 1] = p1;
        g_h2f4[n * 3 + 2] = p2;
        #pragma unroll
        for (int h = 0; h < NH; h++)
            g_ad2[n * NH + h] = a2h[h] * __ldg(&ad2w[h]);
    }
}

// ---- FUSED2: layer2 softmax+agg + head-mean + Wlin + sigmoid ----
__global__ void k_fused2(const float* __restrict__ b2, const float* __restrict__ Wlin,
                         float* __restrict__ out, int N) {
    int warp = (blockIdx.x * blockDim.x + threadIdx.x) >> 5;
    int lane = threadIdx.x & 31;
    if (warp >= N) return;
    int n = warp;
    int row = g_rowptr[n], end = g_rowptr[n + 1];

    float adh[NH], ceh[NH];
    #pragma unroll
    for (int h = 0; h < NH; h++) {
        adh[h] = __ldg(&g_ad2[n * NH + h]);
        ceh[h] = g_ce2[h];
    }
    float acch[NH] = {0.f, 0.f, 0.f, 0.f, 0.f};
    float denh[NH] = {0.f, 0.f, 0.f, 0.f, 0.f};

    for (int base = row; base < end; base += 32) {
        int e = base + lane;
        if (e < end) {
            int2 r = g_edge[e];
            int s = r.x;
            float av = __int_as_float(r.y);
            float4 p0 = __ldg(&g_h2f4[s * 3 + 0]);
            float4 p1 = __ldg(&g_h2f4[s * 3 + 1]);
            float4 p2 = __ldg(&g_h2f4[s * 3 + 2]);
            float h2v[NH]  = {p0.x, p0.z, p1.x, p1.z, p2.x};
            float as2v[NH] = {p0.y, p0.w, p1.y, p1.w, p2.y};
            #pragma unroll
            for (int h = 0; h < NH; h++) {
                float l = as2v[h] + adh[h] + av * ceh[h];
                l = l > 0.f ? l : 0.2f * l;
                float ex = __expf(l);
                denh[h] += ex;
                acch[h] = fmaf(ex, h2v[h], acch[h]);
            }
        }
    }
    #pragma unroll
    for (int h = 0; h < NH; h++)
        #pragma unroll
        for (int o = 16; o; o >>= 1) {
            acch[h] += __shfl_xor_sync(~0u, acch[h], o);
            denh[h] += __shfl_xor_sync(~0u, denh[h], o);
        }
    if (lane == 0) {
        float ssum = 0.f;
        #pragma unroll
        for (int h = 0; h < NH; h++) ssum += acch[h] / (denh[h] + 1e-16f);
        float y = (ssum * (1.0f / NH) + __ldg(&b2[0])) * __ldg(&Wlin[0]);
        out[n] = 1.0f / (1.0f + expf(-y));
    }
}

extern "C" void kernel_launch(void* const* d_in, const int* in_sizes, int n_in,
                              void* d_out, int out_size) {
    const float* x      = (const float*)d_in[0];
    const float* ea     = (const float*)d_in[1];
    const int*   src    = (const int*)d_in[2];
    const int*   dst    = (const int*)d_in[3];
    const float* W1     = (const float*)d_in[4];
    const float* a_src1 = (const float*)d_in[5];
    const float* a_dst1 = (const float*)d_in[6];
    const float* We1    = (const float*)d_in[7];
    const float* ae1    = (const float*)d_in[8];
    const float* b1     = (const float*)d_in[9];
    const float* W2     = (const float*)d_in[10];
    const float* a_src2 = (const float*)d_in[11];
    const float* a_dst2 = (const float*)d_in[12];
    const float* We2    = (const float*)d_in[13];
    const float* ae2    = (const float*)d_in[14];
    const float* b2     = (const float*)d_in[15];
    const float* Wlin   = (const float*)d_in[16];

    int N  = in_sizes[0] / 5;
    int E  = in_sizes[2];
    int E2 = E + N;
    float invE = 1.0f / (float)E;

    void* cntp = nullptr; void* easp = nullptr;
    cudaGetSymbolAddress(&cntp, g_cnt);
    cudaGetSymbolAddress(&easp, g_easum);
    cudaMemsetAsync(cntp, 0, N * sizeof(int));
    cudaMemsetAsync(easp, 0, sizeof(float));

    int countBlocks = (E2 + 255) / 256;
    int nodeBlocks  = (N * 32 + 255) / 256;
    k_combo<<<countBlocks + nodeBlocks, 256>>>(dst, ea, x, W1, a_src1, a_dst1, E, N, countBlocks);
    k_scan<<<1, 1024>>>(We1, ae1, We2, ae2, N, E2);
    k_scatter<<<(E2 + 255) / 256, 256>>>(src, dst, ea, E, N, invE);
    k_fused1<<<(N * 32 + 255) / 256, 256>>>(b1, W2, a_src2, a_dst2, N);
    k_fused2<<<(N * 32 + 255) / 256, 256>>>(b2, Wlin, (float*)d_out, N);
}